// round 1
// baseline (speedup 1.0000x reference)
#include <cuda_runtime.h>
#include <math.h>
#include <math_constants.h>

// Problem constants
#define BB 2
#define NN 2048
#define DIMX 768
#define HH 8
#define DKK 64
#define FF 192
#define NBASIS 32
#define LREL 4095            // 2*N - 1
#define QKVW 512             // H * DK

// ---------------- scratch (device globals; no allocation allowed) ----------
__device__ float g_pos[(size_t)LREL * FF];            // 3.1 MB
__device__ float g_relk[(size_t)LREL * QKVW];         // 8.4 MB  [idx][h*64+d]
__device__ float g_q[(size_t)BB * NN * QKVW];         // 8.4 MB  [b][n][h*64+d]
__device__ float g_k[(size_t)BB * NN * QKVW];
__device__ float g_v[(size_t)BB * NN * QKVW];
__device__ float g_o[(size_t)BB * NN * QKVW];
__device__ float g_S[(size_t)BB * HH * NN * NN];      // 268 MB

// ---------------- K1: positional embedding --------------------------------
__global__ void pos_embed_kernel() {
    int row = blockIdx.x;            // 0..4094
    int i = threadIdx.x;             // 0..31  (one basis per lane)
    float dist = (float)(row - (NN - 1));
    float ad = fabsf(dist);

    // exponential: half_life = 2^(3 + 8i/31), f = 2^(-ad/half_life)
    float half_life = exp2f(3.0f + 8.0f * (float)i / 31.0f);
    float f_exp = exp2f(-ad / half_life);

    // central mask: width = 2^(i+1) - 1
    float width = exp2f((float)(i + 1)) - 1.0f;
    float f_cm = (width > ad) ? 1.0f : 0.0f;

    // gamma pdf: stddev=32, mean=64*(i+1)
    float mean = 64.0f * (float)(i + 1);
    float conc = (mean / 32.0f) * (mean / 32.0f);
    float rate = mean / 1024.0f;
    float log_unnorm = (conc - 1.0f) * logf(ad) - rate * ad;   // ad=0 -> -inf, exp->0
    float log_norm = lgammaf(conc) - conc * logf(rate);
    float prob = expf(log_unnorm - log_norm) + 1e-8f;
    float pmax = prob;
    #pragma unroll
    for (int o = 16; o; o >>= 1) pmax = fmaxf(pmax, __shfl_xor_sync(0xFFFFFFFFu, pmax, o));
    float f_g = prob / pmax;

    float sgn = (dist > 0.0f) ? 1.0f : ((dist < 0.0f) ? -1.0f : 0.0f);

    float* out = g_pos + (size_t)row * FF;
    out[i]            = f_exp;
    out[32 + i]       = f_cm;
    out[64 + i]       = f_g;
    out[96 + i]       = sgn * f_exp;
    out[128 + i]      = sgn * f_cm;
    out[160 + i]      = sgn * f_g;
}

// ---------------- K2: generic fp32 GEMM, 64x64 tile, Kt=16 ------------------
// C[M,Nc] = A[M,K] @ B[K,Nc] (+ bias)
__global__ void gemm_kernel(const float* __restrict__ A, const float* __restrict__ B,
                            const float* __restrict__ bias, float* __restrict__ C,
                            int M, int K, int Nc) {
    __shared__ float As[16][65];   // [kk][mm]
    __shared__ float Bs[16][65];   // [kk][nn]
    int tid = threadIdx.x;
    int tx = tid & 15, ty = tid >> 4;
    int m0 = blockIdx.y * 64, n0 = blockIdx.x * 64;
    float acc[4][4] = {};

    for (int k0 = 0; k0 < K; k0 += 16) {
        for (int t = tid; t < 64 * 16; t += 256) {
            int mm = t >> 4, kk = t & 15;
            int m = m0 + mm, k = k0 + kk;
            As[kk][mm] = (m < M && k < K) ? A[(size_t)m * K + k] : 0.0f;
        }
        for (int t = tid; t < 16 * 64; t += 256) {
            int kk = t >> 6, nn = t & 63;
            int k = k0 + kk, n = n0 + nn;
            Bs[kk][nn] = (k < K && n < Nc) ? B[(size_t)k * Nc + n] : 0.0f;
        }
        __syncthreads();
        #pragma unroll
        for (int kk = 0; kk < 16; kk++) {
            float a[4], b[4];
            #pragma unroll
            for (int i = 0; i < 4; i++) a[i] = As[kk][ty * 4 + i];
            #pragma unroll
            for (int j = 0; j < 4; j++) b[j] = Bs[kk][tx * 4 + j];
            #pragma unroll
            for (int i = 0; i < 4; i++)
                #pragma unroll
                for (int j = 0; j < 4; j++) acc[i][j] += a[i] * b[j];
        }
        __syncthreads();
    }
    #pragma unroll
    for (int i = 0; i < 4; i++) {
        int m = m0 + ty * 4 + i;
        if (m >= M) continue;
        #pragma unroll
        for (int j = 0; j < 4; j++) {
            int n = n0 + tx * 4 + j;
            if (n < Nc) C[(size_t)m * Nc + n] = acc[i][j] + (bias ? bias[n] : 0.0f);
        }
    }
}

// ---------------- K3: logits (content + gathered rel) -----------------------
// S[b,h,i,j] = (0.125*q_i + rcb_h) . k_j  +  (0.125*q_i + rpb_h) . relk[j-i+N-1]
// tile: 64 i-rows x 32 j-cols; rel slice = 95 consecutive relk rows
__global__ void logits_kernel(const float* __restrict__ rcb, const float* __restrict__ rpb) {
    __shared__ float Qs[64][65];   // [d][li]
    __shared__ float Ks[64][97];   // [d][lj]  (phase1: 32 used) / [d][rr] (phase2: 95 used)
    int bh = blockIdx.z;
    int b = bh >> 3, h = bh & 7;
    int i0 = blockIdx.y * 64, j0 = blockIdx.x * 32;
    int tid = threadIdx.x;
    int tx = tid & 15, ty = tid >> 4;   // tx: 2 cols each, ty: 4 rows each

    const float* qb = g_q + (size_t)b * NN * QKVW + h * 64;
    const float* kb = g_k + (size_t)b * NN * QKVW + h * 64;

    float acc[4][2] = {};

    // ---- phase 1: content ----
    for (int t = tid; t < 64 * 64; t += 256) {
        int li = t >> 6, d = t & 63;
        Qs[d][li] = qb[(size_t)(i0 + li) * QKVW + d] * 0.125f + rcb[h * 64 + d];
    }
    for (int t = tid; t < 32 * 64; t += 256) {
        int lj = t >> 6, d = t & 63;
        Ks[d][lj] = kb[(size_t)(j0 + lj) * QKVW + d];
    }
    __syncthreads();
    #pragma unroll 4
    for (int d = 0; d < 64; d++) {
        float a[4], bv[2];
        #pragma unroll
        for (int i = 0; i < 4; i++) a[i] = Qs[d][ty * 4 + i];
        #pragma unroll
        for (int j = 0; j < 2; j++) bv[j] = Ks[d][tx * 2 + j];
        #pragma unroll
        for (int i = 0; i < 4; i++)
            #pragma unroll
            for (int j = 0; j < 2; j++) acc[i][j] += a[i] * bv[j];
    }
    __syncthreads();

    // ---- phase 2: relative (gathered Toeplitz band) ----
    int base = j0 - i0 + (NN - 1) - 63;   // relk row for (li=63, lj=0)
    for (int t = tid; t < 64 * 64; t += 256) {
        int li = t >> 6, d = t & 63;
        Qs[d][li] = qb[(size_t)(i0 + li) * QKVW + d] * 0.125f + rpb[h * 64 + d];
    }
    for (int t = tid; t < 95 * 64; t += 256) {
        int rr = t >> 6, d = t & 63;
        Ks[d][rr] = g_relk[(size_t)(base + rr) * QKVW + h * 64 + d];
    }
    __syncthreads();
    #pragma unroll 4
    for (int d = 0; d < 64; d++) {
        float a[4];
        #pragma unroll
        for (int i = 0; i < 4; i++) a[i] = Qs[d][ty * 4 + i];
        #pragma unroll
        for (int i = 0; i < 4; i++) {
            int li = ty * 4 + i;
            #pragma unroll
            for (int j = 0; j < 2; j++) {
                int lj = tx * 2 + j;
                acc[i][j] += a[i] * Ks[d][lj - li + 63];
            }
        }
    }

    size_t Sbase = ((size_t)bh * NN + i0) * NN + j0;
    #pragma unroll
    for (int i = 0; i < 4; i++)
        #pragma unroll
        for (int j = 0; j < 2; j++)
            g_S[Sbase + (size_t)(ty * 4 + i) * NN + tx * 2 + j] = acc[i][j];
}

// ---------------- K4: row softmax over 2048 --------------------------------
__global__ void softmax_kernel() {
    size_t row = blockIdx.x;
    float* Sr = g_S + row * NN;
    int tid = threadIdx.x;
    __shared__ float red[8];
    __shared__ float bcast;

    float vals[8];
    float m = -CUDART_INF_F;
    #pragma unroll
    for (int t = 0; t < 8; t++) {
        vals[t] = Sr[tid + t * 256];
        m = fmaxf(m, vals[t]);
    }
    #pragma unroll
    for (int o = 16; o; o >>= 1) m = fmaxf(m, __shfl_xor_sync(0xFFFFFFFFu, m, o));
    if ((tid & 31) == 0) red[tid >> 5] = m;
    __syncthreads();
    if (tid == 0) {
        float mm = red[0];
        #pragma unroll
        for (int w = 1; w < 8; w++) mm = fmaxf(mm, red[w]);
        bcast = mm;
    }
    __syncthreads();
    m = bcast;

    float s = 0.0f;
    #pragma unroll
    for (int t = 0; t < 8; t++) {
        vals[t] = expf(vals[t] - m);
        s += vals[t];
    }
    #pragma unroll
    for (int o = 16; o; o >>= 1) s += __shfl_xor_sync(0xFFFFFFFFu, s, o);
    __syncthreads();                  // protect red reuse
    if ((tid & 31) == 0) red[tid >> 5] = s;
    __syncthreads();
    if (tid == 0) {
        float ss = 0.0f;
        #pragma unroll
        for (int w = 0; w < 8; w++) ss += red[w];
        bcast = ss;
    }
    __syncthreads();
    float inv = 1.0f / bcast;
    #pragma unroll
    for (int t = 0; t < 8; t++) Sr[tid + t * 256] = vals[t] * inv;
}

// ---------------- K5: O = P @ V  (per b,h: [2048x2048]@[2048x64]) ----------
__global__ void pv_kernel() {
    __shared__ float Ps[32][65];   // [kk][mm]
    __shared__ float Vs[32][65];   // [kk][nn]
    int bh = blockIdx.y;
    int b = bh >> 3, h = bh & 7;
    int i0 = blockIdx.x * 64;
    int tid = threadIdx.x;
    int tx = tid & 15, ty = tid >> 4;

    const float* vb = g_v + (size_t)b * NN * QKVW + h * 64;
    size_t Sbase = ((size_t)bh * NN + i0) * NN;
    float acc[4][4] = {};

    for (int k0 = 0; k0 < NN; k0 += 32) {
        for (int t = tid; t < 64 * 32; t += 256) {
            int mm = t >> 5, kk = t & 31;
            Ps[kk][mm] = g_S[Sbase + (size_t)mm * NN + k0 + kk];
        }
        for (int t = tid; t < 32 * 64; t += 256) {
            int kk = t >> 6, nn = t & 63;
            Vs[kk][nn] = vb[(size_t)(k0 + kk) * QKVW + nn];
        }
        __syncthreads();
        #pragma unroll
        for (int kk = 0; kk < 32; kk++) {
            float a[4], bv[4];
            #pragma unroll
            for (int i = 0; i < 4; i++) a[i] = Ps[kk][ty * 4 + i];
            #pragma unroll
            for (int j = 0; j < 4; j++) bv[j] = Vs[kk][tx * 4 + j];
            #pragma unroll
            for (int i = 0; i < 4; i++)
                #pragma unroll
                for (int j = 0; j < 4; j++) acc[i][j] += a[i] * bv[j];
        }
        __syncthreads();
    }
    #pragma unroll
    for (int i = 0; i < 4; i++)
        #pragma unroll
        for (int j = 0; j < 4; j++)
            g_o[(size_t)(b * NN + i0 + ty * 4 + i) * QKVW + h * 64 + tx * 4 + j] = acc[i][j];
}

// ---------------- launch ----------------------------------------------------
static float* sym_addr(const void* sym) {
    void* p = nullptr;
    cudaGetSymbolAddress(&p, sym);
    return (float*)p;
}

extern "C" void kernel_launch(void* const* d_in, const int* in_sizes, int n_in,
                              void* d_out, int out_size) {
    const float* x    = (const float*)d_in[0];   // [2,2048,768]
    const float* Wq   = (const float*)d_in[1];   // [768,512]
    const float* Wk   = (const float*)d_in[2];
    const float* Wv   = (const float*)d_in[3];
    const float* Wrel = (const float*)d_in[4];   // [192,512]
    const float* Wout = (const float*)d_in[5];   // [512,768]
    const float* bout = (const float*)d_in[6];   // [768]
    const float* rcb  = (const float*)d_in[7];   // [1,8,1,64] -> 512
    const float* rpb  = (const float*)d_in[8];
    float* out = (float*)d_out;

    float* p_pos  = sym_addr(g_pos);
    float* p_relk = sym_addr(g_relk);
    float* p_q    = sym_addr(g_q);
    float* p_k    = sym_addr(g_k);
    float* p_v    = sym_addr(g_v);
    float* p_o    = sym_addr(g_o);

    // 1. positional embedding
    pos_embed_kernel<<<LREL, 32>>>();

    // 2. rel_k = pos @ Wrel : [4095,192]@[192,512]
    gemm_kernel<<<dim3(QKVW / 64, (LREL + 63) / 64), 256>>>(p_pos, Wrel, nullptr, p_relk,
                                                            LREL, FF, QKVW);

    // 3. q,k,v projections: [4096,768]@[768,512]
    gemm_kernel<<<dim3(QKVW / 64, (BB * NN) / 64), 256>>>(x, Wq, nullptr, p_q,
                                                          BB * NN, DIMX, QKVW);
    gemm_kernel<<<dim3(QKVW / 64, (BB * NN) / 64), 256>>>(x, Wk, nullptr, p_k,
                                                          BB * NN, DIMX, QKVW);
    gemm_kernel<<<dim3(QKVW / 64, (BB * NN) / 64), 256>>>(x, Wv, nullptr, p_v,
                                                          BB * NN, DIMX, QKVW);

    // 4. logits (content + gathered rel)
    logits_kernel<<<dim3(NN / 32, NN / 64, BB * HH), 256>>>(rcb, rpb);

    // 5. softmax over rows
    softmax_kernel<<<BB * HH * NN, 256>>>();

    // 6. O = P @ V
    pv_kernel<<<dim3(NN / 64, BB * HH), 256>>>();

    // 7. out = O @ Wout + b_out : [4096,512]@[512,768]
    gemm_kernel<<<dim3(DIMX / 64, (BB * NN) / 64), 256>>>(p_o, Wout, bout, out,
                                                          BB * NN, QKVW, DIMX);
}